// round 1
// baseline (speedup 1.0000x reference)
#include <cuda_runtime.h>

// CapsNet dynamic routing, fully fused GEMM formulation.
// x: [256, 2401, 8] fp32   W: [2401, 8, 16, 8] fp32   out: [256, 8, 16] fp32
//
// Per routing iteration:
//   M[(i,d),(o,c)] = softmax(b)[i,o] * W[i,o,c,d]          (build_M)
//   S[b,(o,c)]     = X[b,(i,d)] @ M                        (gemm_S, split-K partials)
//   V              = squash(reduce(S))                     (reduce_squash)
//   Y[(i,d),(o,c)] = X^T @ V ; b[i,o] += <W_i_o, Y_i>/256  (gemm_Ya, fused epilogue)

#define IN_CAPS 2401
#define OUT_CAPS 8
#define OUT_SIZE 16
#define IN_SIZE 8
#define BATCH 256
#define KTOT (IN_CAPS * IN_SIZE)     // 19208
#define NOC (OUT_CAPS * OUT_SIZE)    // 128
#define NSPLIT 73
#define CHUNK 264                    // 72*264 + 200 = 19208, both multiples of 8

typedef unsigned long long ull;

__device__ float g_M[(size_t)KTOT * NOC];              // 9.83 MB
__device__ float g_Spart[(size_t)NSPLIT * BATCH * NOC]; // 9.57 MB
__device__ float g_V[BATCH * NOC];
__device__ float g_b[IN_CAPS * OUT_CAPS];

__device__ __forceinline__ void ffma2(ull& acc, ull a, ull b) {
    asm("fma.rn.f32x2 %0, %1, %2, %0;" : "+l"(acc) : "l"(a), "l"(b));
}
__device__ __forceinline__ ull pack2(float x) {
    ull r;
    unsigned u = __float_as_uint(x);
    asm("mov.b64 %0, {%1, %1};" : "=l"(r) : "r"(u));
    return r;
}

// ---------------------------------------------------------------------------
__global__ void init_b_kernel() {
    int t = blockIdx.x * blockDim.x + threadIdx.x;
    if (t < IN_CAPS * OUT_CAPS) g_b[t] = 0.0f;
}

// ---------------------------------------------------------------------------
// grid: 2401 blocks x 128 threads. thread t = o*16 + c.
__global__ void __launch_bounds__(128) build_M_kernel(const float* __restrict__ W) {
    int i = blockIdx.x;
    int t = threadIdx.x;

    // softmax over the 8 output capsules (uniform loads, L1-broadcast)
    float bv[8];
    float mx = -1e30f;
#pragma unroll
    for (int o = 0; o < 8; o++) { bv[o] = g_b[i * 8 + o]; mx = fmaxf(mx, bv[o]); }
    float sum = 0.0f;
#pragma unroll
    for (int o = 0; o < 8; o++) { bv[o] = expf(bv[o] - mx); sum += bv[o]; }
    float c = bv[t >> 4] / sum;

    const float4* w4 = reinterpret_cast<const float4*>(W + (size_t)i * 1024 + t * 8);
    float4 wa = w4[0], wb = w4[1];
    float wv[8] = {wa.x, wa.y, wa.z, wa.w, wb.x, wb.y, wb.z, wb.w};
#pragma unroll
    for (int d = 0; d < 8; d++)
        g_M[(size_t)(i * 8 + d) * NOC + t] = c * wv[d];
}

// ---------------------------------------------------------------------------
// S = X @ M with split-K partials.
// grid (4, NSPLIT), 256 threads. Tile: 64 batch rows x 128 cols.
// Thread (tx,ty) 16x16: rows ty*4+r, cols jj*32 + tx*2 (coalesced, conflict-free).
__global__ void __launch_bounds__(256) gemm_S_kernel(const float* __restrict__ X) {
    __shared__ float Xs[8][64];
    __shared__ float Ms[8][128];

    int b0 = blockIdx.x * 64;
    int kstart = blockIdx.y * CHUNK;
    int kend = min(kstart + CHUNK, KTOT);
    int t = threadIdx.x;
    int tx = t & 15, ty = t >> 4;

    ull acc[4][4];
#pragma unroll
    for (int r = 0; r < 4; r++)
#pragma unroll
        for (int j = 0; j < 4; j++) acc[r][j] = 0ull;

    int ld_bb = t >> 2;            // 0..63
    int ld_kp = (t & 3) * 2;       // 0,2,4,6
    int ld_kk = t >> 5;            // 0..7
    int ld_n4 = (t & 31) * 4;      // 0..124

    for (int k0 = kstart; k0 < kend; k0 += 8) {
        float2 xv = *reinterpret_cast<const float2*>(
            X + (size_t)(b0 + ld_bb) * KTOT + k0 + ld_kp);
        Xs[ld_kp][ld_bb] = xv.x;
        Xs[ld_kp + 1][ld_bb] = xv.y;

        float4 mv = *reinterpret_cast<const float4*>(
            g_M + (size_t)(k0 + ld_kk) * NOC + ld_n4);
        *reinterpret_cast<float4*>(&Ms[ld_kk][ld_n4]) = mv;
        __syncthreads();

#pragma unroll
        for (int kk = 0; kk < 8; kk++) {
            ull mv2[4];
#pragma unroll
            for (int jj = 0; jj < 4; jj++)
                mv2[jj] = *reinterpret_cast<ull*>(&Ms[kk][jj * 32 + tx * 2]);
#pragma unroll
            for (int r = 0; r < 4; r++) {
                ull a = pack2(Xs[kk][ty * 4 + r]);
#pragma unroll
                for (int jj = 0; jj < 4; jj++) ffma2(acc[r][jj], a, mv2[jj]);
            }
        }
        __syncthreads();
    }

    float* out = g_Spart + (size_t)blockIdx.y * BATCH * NOC;
#pragma unroll
    for (int r = 0; r < 4; r++) {
        int bb = b0 + ty * 4 + r;
#pragma unroll
        for (int jj = 0; jj < 4; jj++) {
            *reinterpret_cast<float2*>(out + (size_t)bb * NOC + jj * 32 + tx * 2) =
                *reinterpret_cast<float2*>(&acc[r][jj]);
        }
    }
}

// ---------------------------------------------------------------------------
// Sum split-K partials + squash. grid 128 x 256 threads (32768 elems).
__global__ void __launch_bounds__(256) reduce_squash_kernel(float* __restrict__ out, int last) {
    int idx = blockIdx.x * 256 + threadIdx.x;
    float s = 0.0f;
#pragma unroll 8
    for (int p = 0; p < NSPLIT; p++)
        s += g_Spart[(size_t)p * BATCH * NOC + idx];

    float msq = s * s;
#pragma unroll
    for (int off = 8; off > 0; off >>= 1)
        msq += __shfl_xor_sync(0xffffffffu, msq, off);

    float mag = sqrtf(msq);
    float v = s * (mag / (1.0f + msq));
    g_V[idx] = v;
    if (last) out[idx] = v;
}

// ---------------------------------------------------------------------------
// Y = X^T @ V (tile 64 rows x 128 cols, K=256) with fused b-update epilogue.
// grid 301 blocks x 256 threads. Block owns rows [r0, r0+64) => capsules
// [r0/8, r0/8+8), disjoint across blocks -> race-free g_b updates.
__global__ void __launch_bounds__(256) gemm_Ya_kernel(const float* __restrict__ X,
                                                      const float* __restrict__ W) {
    __shared__ float Xts[8][64];
    __shared__ float Vs[8][128];
    __shared__ float Ysh[64][128];

    int r0 = blockIdx.x * 64;
    int t = threadIdx.x;
    int tx = t & 15, ty = t >> 4;

    ull acc[4][4];
#pragma unroll
    for (int r = 0; r < 4; r++)
#pragma unroll
        for (int j = 0; j < 4; j++) acc[r][j] = 0ull;

    int ld_kk = t >> 5;           // 0..7
    int ld_rr2 = (t & 31) * 2;    // 0..62
    int ld_n4 = (t & 31) * 4;     // 0..124

    for (int k0 = 0; k0 < BATCH; k0 += 8) {
        int r = r0 + ld_rr2;
        float2 xv;
        if (r + 2 <= KTOT) {
            xv = *reinterpret_cast<const float2*>(X + (size_t)(k0 + ld_kk) * KTOT + r);
        } else {
            xv.x = 0.0f; xv.y = 0.0f;
        }
        Xts[ld_kk][ld_rr2] = xv.x;
        Xts[ld_kk][ld_rr2 + 1] = xv.y;

        float4 vv = *reinterpret_cast<const float4*>(g_V + (size_t)(k0 + ld_kk) * NOC + ld_n4);
        *reinterpret_cast<float4*>(&Vs[ld_kk][ld_n4]) = vv;
        __syncthreads();

#pragma unroll
        for (int kk = 0; kk < 8; kk++) {
            ull mv2[4];
#pragma unroll
            for (int jj = 0; jj < 4; jj++)
                mv2[jj] = *reinterpret_cast<ull*>(&Vs[kk][jj * 32 + tx * 2]);
#pragma unroll
            for (int r4 = 0; r4 < 4; r4++) {
                ull a = pack2(Xts[kk][ty * 4 + r4]);
#pragma unroll
                for (int jj = 0; jj < 4; jj++) ffma2(acc[r4][jj], a, mv2[jj]);
            }
        }
        __syncthreads();
    }

    // Stage Y tile to shared for the agreement reduction.
#pragma unroll
    for (int r4 = 0; r4 < 4; r4++)
#pragma unroll
        for (int jj = 0; jj < 4; jj++)
            *reinterpret_cast<float2*>(&Ysh[ty * 4 + r4][jj * 32 + tx * 2]) =
                *reinterpret_cast<float2*>(&acc[r4][jj]);
    __syncthreads();

    // a[i,o] = (1/B) * sum_{c,d} W[i,o,c,d] * Y[(i*8+d),(o*16+c)] ; b += a
    if (t < 64) {
        int il = t >> 3;
        int o = t & 7;
        int i = r0 / 8 + il;
        if (i < IN_CAPS) {
            const float4* w4 = reinterpret_cast<const float4*>(W + (size_t)i * 1024 + o * 128);
            float sum = 0.0f;
#pragma unroll
            for (int c = 0; c < 16; c++) {
                float4 wa = w4[c * 2];
                float4 wb = w4[c * 2 + 1];
                int col = o * 16 + c;
                int rb = il * 8;
                sum += wa.x * Ysh[rb + 0][col] + wa.y * Ysh[rb + 1][col] +
                       wa.z * Ysh[rb + 2][col] + wa.w * Ysh[rb + 3][col] +
                       wb.x * Ysh[rb + 4][col] + wb.y * Ysh[rb + 5][col] +
                       wb.z * Ysh[rb + 6][col] + wb.w * Ysh[rb + 7][col];
            }
            g_b[i * 8 + o] += sum * (1.0f / 256.0f);
        }
    }
}

// ---------------------------------------------------------------------------
extern "C" void kernel_launch(void* const* d_in, const int* in_sizes, int n_in,
                              void* d_out, int out_size) {
    const float* x;
    const float* W;
    if (in_sizes[0] == BATCH * IN_CAPS * IN_SIZE) {
        x = (const float*)d_in[0];
        W = (const float*)d_in[1];
    } else {
        x = (const float*)d_in[1];
        W = (const float*)d_in[0];
    }
    float* out = (float*)d_out;

    init_b_kernel<<<(IN_CAPS * OUT_CAPS + 255) / 256, 256>>>();

    for (int it = 0; it < 3; it++) {
        build_M_kernel<<<IN_CAPS, 128>>>(W);
        gemm_S_kernel<<<dim3(4, NSPLIT), 256>>>(x);
        reduce_squash_kernel<<<BATCH * NOC / 256, 256>>>(out, it == 2 ? 1 : 0);
        if (it < 2) {
            gemm_Ya_kernel<<<(KTOT + 63) / 64, 256>>>(x, W);
        }
    }
}

// round 2
// speedup vs baseline: 1.2574x; 1.2574x over previous
#include <cuda_runtime.h>

// CapsNet dynamic routing, GEMM formulation, fused scaling, 8x8 register tiles.
// x: [256, 2401, 8] fp32   W: [2401, 8, 16, 8] fp32   out: [256, 8, 16] fp32

#define IN_CAPS 2401
#define BATCH 256
#define KTOT 19208                 // 2401*8
#define NOC 128                    // 8*16
#define NSPLIT 73
#define CHUNK 264                  // 72*264 + 200 = 19208, multiples of 8

typedef unsigned long long ull;

__device__ float g_Spart[(size_t)NSPLIT * BATCH * NOC];  // 9.57 MB
__device__ float g_V[BATCH * NOC];
__device__ float g_b[IN_CAPS * 8];
__device__ float g_C[IN_CAPS * 8];

__device__ __forceinline__ void ffma2(ull& acc, ull a, ull b) {
    asm("fma.rn.f32x2 %0, %1, %2, %0;" : "+l"(acc) : "l"(a), "l"(b));
}
__device__ __forceinline__ ull pack2(float x) {
    ull r;
    unsigned u = __float_as_uint(x);
    asm("mov.b64 %0, {%1, %1};" : "=l"(r) : "r"(u));
    return r;
}

// ---------------------------------------------------------------------------
__global__ void init_kernel() {
    int t = blockIdx.x * blockDim.x + threadIdx.x;
    if (t < IN_CAPS * 8) { g_b[t] = 0.0f; g_C[t] = 0.125f; }
}

// softmax over o for each capsule i
__global__ void __launch_bounds__(128) compute_C_kernel() {
    int i = blockIdx.x * 128 + threadIdx.x;
    if (i >= IN_CAPS) return;
    float4 a = *reinterpret_cast<const float4*>(&g_b[i * 8]);
    float4 b = *reinterpret_cast<const float4*>(&g_b[i * 8 + 4]);
    float bv[8] = {a.x, a.y, a.z, a.w, b.x, b.y, b.z, b.w};
    float mx = -1e30f;
#pragma unroll
    for (int o = 0; o < 8; o++) mx = fmaxf(mx, bv[o]);
    float sum = 0.0f;
#pragma unroll
    for (int o = 0; o < 8; o++) { bv[o] = expf(bv[o] - mx); sum += bv[o]; }
    float inv = 1.0f / sum;
    float4 c0 = {bv[0] * inv, bv[1] * inv, bv[2] * inv, bv[3] * inv};
    float4 c1 = {bv[4] * inv, bv[5] * inv, bv[6] * inv, bv[7] * inv};
    *reinterpret_cast<float4*>(&g_C[i * 8]) = c0;
    *reinterpret_cast<float4*>(&g_C[i * 8 + 4]) = c1;
}

// ---------------------------------------------------------------------------
// S = X @ (C .* W), split-K partials. grid (2, NSPLIT) x 256 thr.
// CTA tile 128 batch x 128 cols, per-thread 8x8, prefetched slabs.
__global__ void __launch_bounds__(256, 1) gemm_S_kernel(const float* __restrict__ X,
                                                        const float* __restrict__ W) {
    __shared__ float Xs[8][132];
    __shared__ float Ms[8][132];

    int b0 = blockIdx.x * 128;
    int kstart = blockIdx.y * CHUNK;
    int kend = min(kstart + CHUNK, KTOT);
    int t = threadIdx.x;
    int tx = t & 15, ty = t >> 4;

    ull acc[8][4];
#pragma unroll
    for (int r = 0; r < 8; r++)
#pragma unroll
        for (int j = 0; j < 4; j++) acc[r][j] = 0ull;

    int xbb = t >> 1, xkp = (t & 1) * 4;
    int wl = t * 4;
    int wo = wl >> 7, wc = (wl >> 3) & 15, wd = wl & 7;
    int wcol = wo * 16 + wc;

    // prefetch slab 0
    float4 xv = *reinterpret_cast<const float4*>(X + (size_t)(b0 + xbb) * KTOT + kstart + xkp);
    float4 wv = *reinterpret_cast<const float4*>(W + (size_t)(kstart >> 3) * 1024 + wl);
    float cc = g_C[(kstart >> 3) * 8 + wo];

    for (int k0 = kstart; k0 < kend; k0 += 8) {
        __syncthreads();
        Xs[xkp + 0][xbb] = xv.x; Xs[xkp + 1][xbb] = xv.y;
        Xs[xkp + 2][xbb] = xv.z; Xs[xkp + 3][xbb] = xv.w;
        Ms[wd + 0][wcol] = cc * wv.x; Ms[wd + 1][wcol] = cc * wv.y;
        Ms[wd + 2][wcol] = cc * wv.z; Ms[wd + 3][wcol] = cc * wv.w;
        __syncthreads();

        int kn = k0 + 8;
        if (kn < kend) {  // prefetch next slab (hides LDG behind compute)
            xv = *reinterpret_cast<const float4*>(X + (size_t)(b0 + xbb) * KTOT + kn + xkp);
            wv = *reinterpret_cast<const float4*>(W + (size_t)(kn >> 3) * 1024 + wl);
            cc = g_C[(kn >> 3) * 8 + wo];
        }

#pragma unroll
        for (int kk = 0; kk < 8; kk++) {
            ull mv[4];
#pragma unroll
            for (int jj = 0; jj < 4; jj++)
                mv[jj] = *reinterpret_cast<const ull*>(&Ms[kk][jj * 32 + tx * 2]);
#pragma unroll
            for (int rr = 0; rr < 8; rr++) {
                ull a = pack2(Xs[kk][ty * 8 + rr]);
#pragma unroll
                for (int jj = 0; jj < 4; jj++) ffma2(acc[rr][jj], a, mv[jj]);
            }
        }
    }

    float* out = g_Spart + (size_t)blockIdx.y * (BATCH * NOC);
#pragma unroll
    for (int rr = 0; rr < 8; rr++) {
        int bb = b0 + ty * 8 + rr;
#pragma unroll
        for (int jj = 0; jj < 4; jj++)
            *reinterpret_cast<float2*>(out + (size_t)bb * NOC + jj * 32 + tx * 2) =
                *reinterpret_cast<float2*>(&acc[rr][jj]);
    }
}

// ---------------------------------------------------------------------------
// Sum split-K partials (4-way K parallel per block) + squash.
// grid 256 x 512 thr: 128 outputs per block, 4 partial lanes each.
__global__ void __launch_bounds__(512) reduce_squash_kernel(float* __restrict__ out, int last) {
    __shared__ float part[3][128];
    int il = threadIdx.x & 127;
    int q = threadIdx.x >> 7;
    int idx = blockIdx.x * 128 + il;

    int p0 = (q == 0) ? 0 : (19 + (q - 1) * 18);
    int p1 = p0 + ((q == 0) ? 19 : 18);
    float s = 0.0f;
#pragma unroll 8
    for (int p = p0; p < p1; p++)
        s += g_Spart[(size_t)p * (BATCH * NOC) + idx];

    if (q) part[q - 1][il] = s;
    __syncthreads();
    if (q == 0) {
        s += part[0][il] + part[1][il] + part[2][il];
        float msq = s * s;
#pragma unroll
        for (int off = 8; off > 0; off >>= 1)
            msq += __shfl_xor_sync(0xffffffffu, msq, off);
        float mag = sqrtf(msq);
        float v = s * (mag / (1.0f + msq));
        g_V[idx] = v;
        if (last) out[idx] = v;
    }
}

// ---------------------------------------------------------------------------
// Y = X^T @ V with fused agreement + b update from accumulator registers.
// grid 151 x 256 thr; CTA tile 128 K-rows x 128 cols. Thread ty owns capsule
// i = r0/8 + ty (all 8 d-rows) -> shfl-reduce agreement, race-free b writes.
__global__ void __launch_bounds__(256, 1) gemm_Ya_kernel(const float* __restrict__ X,
                                                         const float* __restrict__ W) {
    __shared__ float Xts[8][132];
    __shared__ float Vs[8][132];

    int r0 = blockIdx.x * 128;
    int t = threadIdx.x;
    int tx = t & 15, ty = t >> 4;

    ull acc[8][4];
#pragma unroll
    for (int r = 0; r < 8; r++)
#pragma unroll
        for (int j = 0; j < 4; j++) acc[r][j] = 0ull;

    int lkk = t >> 5, lq = (t & 31) * 4;
    bool xok = (r0 + lq) < KTOT;

    float4 xv = xok ? *reinterpret_cast<const float4*>(X + (size_t)lkk * KTOT + r0 + lq)
                    : make_float4(0.f, 0.f, 0.f, 0.f);
    float4 vv = *reinterpret_cast<const float4*>(g_V + lkk * NOC + lq);

    for (int k0 = 0; k0 < BATCH; k0 += 8) {
        __syncthreads();
        *reinterpret_cast<float4*>(&Xts[lkk][lq]) = xv;
        *reinterpret_cast<float4*>(&Vs[lkk][lq]) = vv;
        __syncthreads();

        int kn = k0 + 8;
        if (kn < BATCH) {
            xv = xok ? *reinterpret_cast<const float4*>(X + (size_t)(kn + lkk) * KTOT + r0 + lq)
                     : make_float4(0.f, 0.f, 0.f, 0.f);
            vv = *reinterpret_cast<const float4*>(g_V + (kn + lkk) * NOC + lq);
        }

#pragma unroll
        for (int kk = 0; kk < 8; kk++) {
            ull mv[4];
#pragma unroll
            for (int jj = 0; jj < 4; jj++)
                mv[jj] = *reinterpret_cast<const ull*>(&Vs[kk][jj * 32 + tx * 2]);
#pragma unroll
            for (int rr = 0; rr < 8; rr++) {
                ull a = pack2(Xts[kk][ty * 8 + rr]);
#pragma unroll
                for (int jj = 0; jj < 4; jj++) ffma2(acc[rr][jj], a, mv[jj]);
            }
        }
    }

    // Agreement: a[i,o] = (1/B) sum_{c,d} W[i,o,c,d] * Y[(i,d),(o,c)]
    int i = r0 / 8 + ty;
    int iw = min(i, IN_CAPS - 1);
    int ohi = tx >> 3;
    int c = (tx & 7) * 2;
    float s[4];
#pragma unroll
    for (int jj = 0; jj < 4; jj++) {
        int oo = jj * 2 + ohi;
        const float4* wp = reinterpret_cast<const float4*>(W + (size_t)iw * 1024 + oo * 128 + c * 8);
        float4 w0 = wp[0], w1 = wp[1], w2 = wp[2], w3 = wp[3];
        float wlo[8] = {w0.x, w0.y, w0.z, w0.w, w1.x, w1.y, w1.z, w1.w};
        float whi[8] = {w2.x, w2.y, w2.z, w2.w, w3.x, w3.y, w3.z, w3.w};
        float sum = 0.0f;
#pragma unroll
        for (int d = 0; d < 8; d++) {
            float2 y = *reinterpret_cast<float2*>(&acc[d][jj]);
            sum += wlo[d] * y.x + whi[d] * y.y;
        }
        s[jj] = sum;
    }
#pragma unroll
    for (int jj = 0; jj < 4; jj++) {
        s[jj] += __shfl_xor_sync(0xffffffffu, s[jj], 1);
        s[jj] += __shfl_xor_sync(0xffffffffu, s[jj], 2);
        s[jj] += __shfl_xor_sync(0xffffffffu, s[jj], 4);
    }
    if ((tx & 7) == 0 && i < IN_CAPS) {
#pragma unroll
        for (int jj = 0; jj < 4; jj++)
            g_b[i * 8 + jj * 2 + ohi] += s[jj] * (1.0f / 256.0f);
    }
}

// ---------------------------------------------------------------------------
extern "C" void kernel_launch(void* const* d_in, const int* in_sizes, int n_in,
                              void* d_out, int out_size) {
    const float* x;
    const float* W;
    if (in_sizes[0] == BATCH * KTOT) {
        x = (const float*)d_in[0];
        W = (const float*)d_in[1];
    } else {
        x = (const float*)d_in[1];
        W = (const float*)d_in[0];
    }
    float* out = (float*)d_out;

    init_kernel<<<76, 256>>>();

    for (int it = 0; it < 3; it++) {
        gemm_S_kernel<<<dim3(2, NSPLIT), 256>>>(x, W);
        reduce_squash_kernel<<<256, 512>>>(out, it == 2 ? 1 : 0);
        if (it < 2) {
            gemm_Ya_kernel<<<(KTOT + 127) / 128, 256>>>(x, W);
            compute_C_kernel<<<19, 128>>>();
        }
    }
}

// round 3
// speedup vs baseline: 1.3054x; 1.0382x over previous
#include <cuda_runtime.h>

// CapsNet dynamic routing, GEMM formulation, fused scaling, 8x8 register tiles.
// R3: occupancy-2 launch bounds on both GEMMs. gemm_Ya's 151 CTAs previously ran
// as 148+3 waves (2x time); at occ=2 (n_conc=296) it is a single wave.
// x: [256, 2401, 8] fp32   W: [2401, 8, 16, 8] fp32   out: [256, 8, 16] fp32

#define IN_CAPS 2401
#define BATCH 256
#define KTOT 19208                 // 2401*8
#define NOC 128                    // 8*16
#define NSPLIT 73
#define CHUNK 264                  // 72*264 + 200 = 19208, multiples of 8

typedef unsigned long long ull;

__device__ float g_Spart[(size_t)NSPLIT * BATCH * NOC];  // 9.57 MB
__device__ float g_V[BATCH * NOC];
__device__ float g_b[IN_CAPS * 8];
__device__ float g_C[IN_CAPS * 8];

__device__ __forceinline__ void ffma2(ull& acc, ull a, ull b) {
    asm("fma.rn.f32x2 %0, %1, %2, %0;" : "+l"(acc) : "l"(a), "l"(b));
}
__device__ __forceinline__ ull pack2(float x) {
    ull r;
    unsigned u = __float_as_uint(x);
    asm("mov.b64 %0, {%1, %1};" : "=l"(r) : "r"(u));
    return r;
}

// ---------------------------------------------------------------------------
__global__ void init_kernel() {
    int t = blockIdx.x * blockDim.x + threadIdx.x;
    if (t < IN_CAPS * 8) { g_b[t] = 0.0f; g_C[t] = 0.125f; }
}

// softmax over o for each capsule i
__global__ void __launch_bounds__(128) compute_C_kernel() {
    int i = blockIdx.x * 128 + threadIdx.x;
    if (i >= IN_CAPS) return;
    float4 a = *reinterpret_cast<const float4*>(&g_b[i * 8]);
    float4 b = *reinterpret_cast<const float4*>(&g_b[i * 8 + 4]);
    float bv[8] = {a.x, a.y, a.z, a.w, b.x, b.y, b.z, b.w};
    float mx = -1e30f;
#pragma unroll
    for (int o = 0; o < 8; o++) mx = fmaxf(mx, bv[o]);
    float sum = 0.0f;
#pragma unroll
    for (int o = 0; o < 8; o++) { bv[o] = expf(bv[o] - mx); sum += bv[o]; }
    float inv = 1.0f / sum;
    float4 c0 = {bv[0] * inv, bv[1] * inv, bv[2] * inv, bv[3] * inv};
    float4 c1 = {bv[4] * inv, bv[5] * inv, bv[6] * inv, bv[7] * inv};
    *reinterpret_cast<float4*>(&g_C[i * 8]) = c0;
    *reinterpret_cast<float4*>(&g_C[i * 8 + 4]) = c1;
}

// ---------------------------------------------------------------------------
// S = X @ (C .* W), split-K partials. grid (2, NSPLIT) x 256 thr, occ 2.
// CTA tile 128 batch x 128 cols, per-thread 8x8, prefetched slabs.
__global__ void __launch_bounds__(256, 2) gemm_S_kernel(const float* __restrict__ X,
                                                        const float* __restrict__ W) {
    __shared__ float Xs[8][132];
    __shared__ float Ms[8][132];

    int b0 = blockIdx.x * 128;
    int kstart = blockIdx.y * CHUNK;
    int kend = min(kstart + CHUNK, KTOT);
    int t = threadIdx.x;
    int tx = t & 15, ty = t >> 4;

    ull acc[8][4];
#pragma unroll
    for (int r = 0; r < 8; r++)
#pragma unroll
        for (int j = 0; j < 4; j++) acc[r][j] = 0ull;

    int xbb = t >> 1, xkp = (t & 1) * 4;
    int wl = t * 4;
    int wo = wl >> 7, wc = (wl >> 3) & 15, wd = wl & 7;
    int wcol = wo * 16 + wc;

    // prefetch slab 0
    float4 xv = *reinterpret_cast<const float4*>(X + (size_t)(b0 + xbb) * KTOT + kstart + xkp);
    float4 wv = *reinterpret_cast<const float4*>(W + (size_t)(kstart >> 3) * 1024 + wl);
    float cc = g_C[(kstart >> 3) * 8 + wo];

    for (int k0 = kstart; k0 < kend; k0 += 8) {
        __syncthreads();
        Xs[xkp + 0][xbb] = xv.x; Xs[xkp + 1][xbb] = xv.y;
        Xs[xkp + 2][xbb] = xv.z; Xs[xkp + 3][xbb] = xv.w;
        Ms[wd + 0][wcol] = cc * wv.x; Ms[wd + 1][wcol] = cc * wv.y;
        Ms[wd + 2][wcol] = cc * wv.z; Ms[wd + 3][wcol] = cc * wv.w;
        __syncthreads();

        int kn = k0 + 8;
        if (kn < kend) {  // prefetch next slab (hides LDG behind compute)
            xv = *reinterpret_cast<const float4*>(X + (size_t)(b0 + xbb) * KTOT + kn + xkp);
            wv = *reinterpret_cast<const float4*>(W + (size_t)(kn >> 3) * 1024 + wl);
            cc = g_C[(kn >> 3) * 8 + wo];
        }

#pragma unroll
        for (int kk = 0; kk < 8; kk++) {
            ull mv[4];
#pragma unroll
            for (int jj = 0; jj < 4; jj++)
                mv[jj] = *reinterpret_cast<const ull*>(&Ms[kk][jj * 32 + tx * 2]);
#pragma unroll
            for (int rr = 0; rr < 8; rr++) {
                ull a = pack2(Xs[kk][ty * 8 + rr]);
#pragma unroll
                for (int jj = 0; jj < 4; jj++) ffma2(acc[rr][jj], a, mv[jj]);
            }
        }
    }

    float* out = g_Spart + (size_t)blockIdx.y * (BATCH * NOC);
#pragma unroll
    for (int rr = 0; rr < 8; rr++) {
        int bb = b0 + ty * 8 + rr;
#pragma unroll
        for (int jj = 0; jj < 4; jj++)
            *reinterpret_cast<float2*>(out + (size_t)bb * NOC + jj * 32 + tx * 2) =
                *reinterpret_cast<float2*>(&acc[rr][jj]);
    }
}

// ---------------------------------------------------------------------------
// Sum split-K partials (4-way K parallel per block) + squash.
// grid 256 x 512 thr: 128 outputs per block, 4 partial lanes each.
__global__ void __launch_bounds__(512) reduce_squash_kernel(float* __restrict__ out, int last) {
    __shared__ float part[3][128];
    int il = threadIdx.x & 127;
    int q = threadIdx.x >> 7;
    int idx = blockIdx.x * 128 + il;

    int p0 = (q == 0) ? 0 : (19 + (q - 1) * 18);
    int p1 = p0 + ((q == 0) ? 19 : 18);
    float s = 0.0f;
#pragma unroll 8
    for (int p = p0; p < p1; p++)
        s += g_Spart[(size_t)p * (BATCH * NOC) + idx];

    if (q) part[q - 1][il] = s;
    __syncthreads();
    if (q == 0) {
        s += part[0][il] + part[1][il] + part[2][il];
        float msq = s * s;
#pragma unroll
        for (int off = 8; off > 0; off >>= 1)
            msq += __shfl_xor_sync(0xffffffffu, msq, off);
        float mag = sqrtf(msq);
        float v = s * (mag / (1.0f + msq));
        g_V[idx] = v;
        if (last) out[idx] = v;
    }
}

// ---------------------------------------------------------------------------
// Y = X^T @ V with fused agreement + b update from accumulator registers.
// grid 151 x 256 thr, occ 2 (single wave at n_conc=296).
// CTA tile 128 K-rows x 128 cols. Thread ty owns capsule i = r0/8 + ty.
__global__ void __launch_bounds__(256, 2) gemm_Ya_kernel(const float* __restrict__ X,
                                                         const float* __restrict__ W) {
    __shared__ float Xts[8][132];
    __shared__ float Vs[8][132];

    int r0 = blockIdx.x * 128;
    int t = threadIdx.x;
    int tx = t & 15, ty = t >> 4;

    ull acc[8][4];
#pragma unroll
    for (int r = 0; r < 8; r++)
#pragma unroll
        for (int j = 0; j < 4; j++) acc[r][j] = 0ull;

    int lkk = t >> 5, lq = (t & 31) * 4;
    bool xok = (r0 + lq) < KTOT;

    float4 xv = xok ? *reinterpret_cast<const float4*>(X + (size_t)lkk * KTOT + r0 + lq)
                    : make_float4(0.f, 0.f, 0.f, 0.f);
    float4 vv = *reinterpret_cast<const float4*>(g_V + lkk * NOC + lq);

    for (int k0 = 0; k0 < BATCH; k0 += 8) {
        __syncthreads();
        *reinterpret_cast<float4*>(&Xts[lkk][lq]) = xv;
        *reinterpret_cast<float4*>(&Vs[lkk][lq]) = vv;
        __syncthreads();

        int kn = k0 + 8;
        if (kn < BATCH) {
            xv = xok ? *reinterpret_cast<const float4*>(X + (size_t)(kn + lkk) * KTOT + r0 + lq)
                     : make_float4(0.f, 0.f, 0.f, 0.f);
            vv = *reinterpret_cast<const float4*>(g_V + (kn + lkk) * NOC + lq);
        }

#pragma unroll
        for (int kk = 0; kk < 8; kk++) {
            ull mv[4];
#pragma unroll
            for (int jj = 0; jj < 4; jj++)
                mv[jj] = *reinterpret_cast<const ull*>(&Vs[kk][jj * 32 + tx * 2]);
#pragma unroll
            for (int rr = 0; rr < 8; rr++) {
                ull a = pack2(Xts[kk][ty * 8 + rr]);
#pragma unroll
                for (int jj = 0; jj < 4; jj++) ffma2(acc[rr][jj], a, mv[jj]);
            }
        }
    }

    // Agreement: a[i,o] = (1/B) sum_{c,d} W[i,o,c,d] * Y[(i,d),(o,c)]
    int i = r0 / 8 + ty;
    int iw = min(i, IN_CAPS - 1);
    int ohi = tx >> 3;
    int c = (tx & 7) * 2;
    float s[4];
#pragma unroll
    for (int jj = 0; jj < 4; jj++) {
        int oo = jj * 2 + ohi;
        const float4* wp = reinterpret_cast<const float4*>(W + (size_t)iw * 1024 + oo * 128 + c * 8);
        float4 w0 = wp[0], w1 = wp[1], w2 = wp[2], w3 = wp[3];
        float wlo[8] = {w0.x, w0.y, w0.z, w0.w, w1.x, w1.y, w1.z, w1.w};
        float whi[8] = {w2.x, w2.y, w2.z, w2.w, w3.x, w3.y, w3.z, w3.w};
        float sum = 0.0f;
#pragma unroll
        for (int d = 0; d < 8; d++) {
            float2 y = *reinterpret_cast<float2*>(&acc[d][jj]);
            sum += wlo[d] * y.x + whi[d] * y.y;
        }
        s[jj] = sum;
    }
#pragma unroll
    for (int jj = 0; jj < 4; jj++) {
        s[jj] += __shfl_xor_sync(0xffffffffu, s[jj], 1);
        s[jj] += __shfl_xor_sync(0xffffffffu, s[jj], 2);
        s[jj] += __shfl_xor_sync(0xffffffffu, s[jj], 4);
    }
    if ((tx & 7) == 0 && i < IN_CAPS) {
#pragma unroll
        for (int jj = 0; jj < 4; jj++)
            g_b[i * 8 + jj * 2 + ohi] += s[jj] * (1.0f / 256.0f);
    }
}

// ---------------------------------------------------------------------------
extern "C" void kernel_launch(void* const* d_in, const int* in_sizes, int n_in,
                              void* d_out, int out_size) {
    const float* x;
    const float* W;
    if (in_sizes[0] == BATCH * KTOT) {
        x = (const float*)d_in[0];
        W = (const float*)d_in[1];
    } else {
        x = (const float*)d_in[1];
        W = (const float*)d_in[0];
    }
    float* out = (float*)d_out;

    init_kernel<<<76, 256>>>();

    for (int it = 0; it < 3; it++) {
        gemm_S_kernel<<<dim3(2, NSPLIT), 256>>>(x, W);
        reduce_squash_kernel<<<256, 512>>>(out, it == 2 ? 1 : 0);
        if (it < 2) {
            gemm_Ya_kernel<<<(KTOT + 127) / 128, 256>>>(x, W);
            compute_C_kernel<<<19, 128>>>();
        }
    }
}

// round 4
// speedup vs baseline: 1.3319x; 1.0203x over previous
#include <cuda_runtime.h>

// CapsNet dynamic routing, GEMM formulation.
// R4: gemm_Ya re-tiled 64 rows x 128 cols, 128 thr/CTA, occ 4 (grid 301 -> 16
// warps/SM resident, single wave). Inner-loop mix identical to the
// roofline-saturating gemm_S (8x8 per-thread FFMA2 tile).
// x: [256, 2401, 8] fp32   W: [2401, 8, 16, 8] fp32   out: [256, 8, 16] fp32

#define IN_CAPS 2401
#define BATCH 256
#define KTOT 19208                 // 2401*8
#define NOC 128                    // 8*16
#define NSPLIT 73
#define CHUNK 264                  // 72*264 + 200 = 19208, multiples of 8

typedef unsigned long long ull;

__device__ float g_Spart[(size_t)NSPLIT * BATCH * NOC];  // 9.57 MB
__device__ float g_V[BATCH * NOC];
__device__ float g_b[IN_CAPS * 8];
__device__ float g_C[IN_CAPS * 8];

__device__ __forceinline__ void ffma2(ull& acc, ull a, ull b) {
    asm("fma.rn.f32x2 %0, %1, %2, %0;" : "+l"(acc) : "l"(a), "l"(b));
}
__device__ __forceinline__ ull pack2(float x) {
    ull r;
    unsigned u = __float_as_uint(x);
    asm("mov.b64 %0, {%1, %1};" : "=l"(r) : "r"(u));
    return r;
}

// ---------------------------------------------------------------------------
__global__ void init_kernel() {
    int t = blockIdx.x * blockDim.x + threadIdx.x;
    if (t < IN_CAPS * 8) { g_b[t] = 0.0f; g_C[t] = 0.125f; }
}

// softmax over o for each capsule i
__global__ void __launch_bounds__(128) compute_C_kernel() {
    int i = blockIdx.x * 128 + threadIdx.x;
    if (i >= IN_CAPS) return;
    float4 a = *reinterpret_cast<const float4*>(&g_b[i * 8]);
    float4 b = *reinterpret_cast<const float4*>(&g_b[i * 8 + 4]);
    float bv[8] = {a.x, a.y, a.z, a.w, b.x, b.y, b.z, b.w};
    float mx = -1e30f;
#pragma unroll
    for (int o = 0; o < 8; o++) mx = fmaxf(mx, bv[o]);
    float sum = 0.0f;
#pragma unroll
    for (int o = 0; o < 8; o++) { bv[o] = expf(bv[o] - mx); sum += bv[o]; }
    float inv = 1.0f / sum;
    float4 c0 = {bv[0] * inv, bv[1] * inv, bv[2] * inv, bv[3] * inv};
    float4 c1 = {bv[4] * inv, bv[5] * inv, bv[6] * inv, bv[7] * inv};
    *reinterpret_cast<float4*>(&g_C[i * 8]) = c0;
    *reinterpret_cast<float4*>(&g_C[i * 8 + 4]) = c1;
}

// ---------------------------------------------------------------------------
// S = X @ (C .* W), split-K partials. grid (2, NSPLIT) x 256 thr.
// CTA tile 128 batch x 128 cols, per-thread 8x8, prefetched slabs.
__global__ void __launch_bounds__(256, 2) gemm_S_kernel(const float* __restrict__ X,
                                                        const float* __restrict__ W) {
    __shared__ float Xs[8][132];
    __shared__ float Ms[8][132];

    int b0 = blockIdx.x * 128;
    int kstart = blockIdx.y * CHUNK;
    int kend = min(kstart + CHUNK, KTOT);
    int t = threadIdx.x;
    int tx = t & 15, ty = t >> 4;

    ull acc[8][4];
#pragma unroll
    for (int r = 0; r < 8; r++)
#pragma unroll
        for (int j = 0; j < 4; j++) acc[r][j] = 0ull;

    int xbb = t >> 1, xkp = (t & 1) * 4;
    int wl = t * 4;
    int wo = wl >> 7, wc = (wl >> 3) & 15, wd = wl & 7;
    int wcol = wo * 16 + wc;

    // prefetch slab 0
    float4 xv = *reinterpret_cast<const float4*>(X + (size_t)(b0 + xbb) * KTOT + kstart + xkp);
    float4 wv = *reinterpret_cast<const float4*>(W + (size_t)(kstart >> 3) * 1024 + wl);
    float cc = g_C[(kstart >> 3) * 8 + wo];

    for (int k0 = kstart; k0 < kend; k0 += 8) {
        __syncthreads();
        Xs[xkp + 0][xbb] = xv.x; Xs[xkp + 1][xbb] = xv.y;
        Xs[xkp + 2][xbb] = xv.z; Xs[xkp + 3][xbb] = xv.w;
        Ms[wd + 0][wcol] = cc * wv.x; Ms[wd + 1][wcol] = cc * wv.y;
        Ms[wd + 2][wcol] = cc * wv.z; Ms[wd + 3][wcol] = cc * wv.w;
        __syncthreads();

        int kn = k0 + 8;
        if (kn < kend) {  // prefetch next slab (hides LDG behind compute)
            xv = *reinterpret_cast<const float4*>(X + (size_t)(b0 + xbb) * KTOT + kn + xkp);
            wv = *reinterpret_cast<const float4*>(W + (size_t)(kn >> 3) * 1024 + wl);
            cc = g_C[(kn >> 3) * 8 + wo];
        }

#pragma unroll
        for (int kk = 0; kk < 8; kk++) {
            ull mv[4];
#pragma unroll
            for (int jj = 0; jj < 4; jj++)
                mv[jj] = *reinterpret_cast<const ull*>(&Ms[kk][jj * 32 + tx * 2]);
#pragma unroll
            for (int rr = 0; rr < 8; rr++) {
                ull a = pack2(Xs[kk][ty * 8 + rr]);
#pragma unroll
                for (int jj = 0; jj < 4; jj++) ffma2(acc[rr][jj], a, mv[jj]);
            }
        }
    }

    float* out = g_Spart + (size_t)blockIdx.y * (BATCH * NOC);
#pragma unroll
    for (int rr = 0; rr < 8; rr++) {
        int bb = b0 + ty * 8 + rr;
#pragma unroll
        for (int jj = 0; jj < 4; jj++)
            *reinterpret_cast<float2*>(out + (size_t)bb * NOC + jj * 32 + tx * 2) =
                *reinterpret_cast<float2*>(&acc[rr][jj]);
    }
}

// ---------------------------------------------------------------------------
// Sum split-K partials (4-way K parallel per block) + squash.
// grid 256 x 512 thr: 128 outputs per block, 4 partial lanes each.
__global__ void __launch_bounds__(512) reduce_squash_kernel(float* __restrict__ out, int last) {
    __shared__ float part[3][128];
    int il = threadIdx.x & 127;
    int q = threadIdx.x >> 7;
    int idx = blockIdx.x * 128 + il;

    int p0 = (q == 0) ? 0 : (19 + (q - 1) * 18);
    int p1 = p0 + ((q == 0) ? 19 : 18);
    float s = 0.0f;
#pragma unroll 8
    for (int p = p0; p < p1; p++)
        s += g_Spart[(size_t)p * (BATCH * NOC) + idx];

    if (q) part[q - 1][il] = s;
    __syncthreads();
    if (q == 0) {
        s += part[0][il] + part[1][il] + part[2][il];
        float msq = s * s;
#pragma unroll
        for (int off = 8; off > 0; off >>= 1)
            msq += __shfl_xor_sync(0xffffffffu, msq, off);
        float mag = sqrtf(msq);
        float v = s * (mag / (1.0f + msq));
        g_V[idx] = v;
        if (last) out[idx] = v;
    }
}

// ---------------------------------------------------------------------------
// Y = X^T @ V with fused agreement + b update from accumulator registers.
// grid 301 x 128 thr, occ 4 -> 16 warps/SM, single wave (301 < 4*148).
// CTA tile 64 K-rows x 128 cols; per-thread 8x8 (same mix as gemm_S).
// Thread group ty (0..7) owns capsule i = r0/8 + ty -> race-free b writes.
__global__ void __launch_bounds__(128, 4) gemm_Ya_kernel(const float* __restrict__ X,
                                                         const float* __restrict__ W) {
    __shared__ float Xts[8][68];
    __shared__ float Vs[8][132];

    int r0 = blockIdx.x * 64;
    int t = threadIdx.x;
    int tx = t & 15, ty = t >> 4;

    ull acc[8][4];
#pragma unroll
    for (int r = 0; r < 8; r++)
#pragma unroll
        for (int j = 0; j < 4; j++) acc[r][j] = 0ull;

    int lkk = t >> 4;            // 0..7 (k-row within slab)
    int lq = (t & 15) * 4;       // 0..60 (col within 64-row tile)
    bool xok = (r0 + lq) < KTOT;

    float4 xv = xok ? *reinterpret_cast<const float4*>(X + (size_t)lkk * KTOT + r0 + lq)
                    : make_float4(0.f, 0.f, 0.f, 0.f);
    float4 va = *reinterpret_cast<const float4*>(g_V + lkk * NOC + lq);
    float4 vb = *reinterpret_cast<const float4*>(g_V + lkk * NOC + lq + 64);

    for (int k0 = 0; k0 < BATCH; k0 += 8) {
        __syncthreads();
        *reinterpret_cast<float4*>(&Xts[lkk][lq]) = xv;
        *reinterpret_cast<float4*>(&Vs[lkk][lq]) = va;
        *reinterpret_cast<float4*>(&Vs[lkk][lq + 64]) = vb;
        __syncthreads();

        int kn = k0 + 8;
        if (kn < BATCH) {
            xv = xok ? *reinterpret_cast<const float4*>(X + (size_t)(kn + lkk) * KTOT + r0 + lq)
                     : make_float4(0.f, 0.f, 0.f, 0.f);
            va = *reinterpret_cast<const float4*>(g_V + (kn + lkk) * NOC + lq);
            vb = *reinterpret_cast<const float4*>(g_V + (kn + lkk) * NOC + lq + 64);
        }

#pragma unroll
        for (int kk = 0; kk < 8; kk++) {
            ull mv[4];
#pragma unroll
            for (int jj = 0; jj < 4; jj++)
                mv[jj] = *reinterpret_cast<const ull*>(&Vs[kk][jj * 32 + tx * 2]);
#pragma unroll
            for (int rr = 0; rr < 8; rr++) {
                ull a = pack2(Xts[kk][ty * 8 + rr]);
#pragma unroll
                for (int jj = 0; jj < 4; jj++) ffma2(acc[rr][jj], a, mv[jj]);
            }
        }
    }

    // Agreement: a[i,o] = (1/B) sum_{c,d} W[i,o,c,d] * Y[(i,d),(o,c)]
    int i = r0 / 8 + ty;
    int iw = min(i, IN_CAPS - 1);
    int ohi = tx >> 3;
    int c = (tx & 7) * 2;
    float s[4];
#pragma unroll
    for (int jj = 0; jj < 4; jj++) {
        int oo = jj * 2 + ohi;
        const float4* wp = reinterpret_cast<const float4*>(W + (size_t)iw * 1024 + oo * 128 + c * 8);
        float4 w0 = wp[0], w1 = wp[1], w2 = wp[2], w3 = wp[3];
        float wlo[8] = {w0.x, w0.y, w0.z, w0.w, w1.x, w1.y, w1.z, w1.w};
        float whi[8] = {w2.x, w2.y, w2.z, w2.w, w3.x, w3.y, w3.z, w3.w};
        float sum = 0.0f;
#pragma unroll
        for (int d = 0; d < 8; d++) {
            float2 y = *reinterpret_cast<float2*>(&acc[d][jj]);
            sum += wlo[d] * y.x + whi[d] * y.y;
        }
        s[jj] = sum;
    }
#pragma unroll
    for (int jj = 0; jj < 4; jj++) {
        s[jj] += __shfl_xor_sync(0xffffffffu, s[jj], 1);
        s[jj] += __shfl_xor_sync(0xffffffffu, s[jj], 2);
        s[jj] += __shfl_xor_sync(0xffffffffu, s[jj], 4);
    }
    if ((tx & 7) == 0 && i < IN_CAPS) {
#pragma unroll
        for (int jj = 0; jj < 4; jj++)
            g_b[i * 8 + jj * 2 + ohi] += s[jj] * (1.0f / 256.0f);
    }
}

// ---------------------------------------------------------------------------
extern "C" void kernel_launch(void* const* d_in, const int* in_sizes, int n_in,
                              void* d_out, int out_size) {
    const float* x;
    const float* W;
    if (in_sizes[0] == BATCH * KTOT) {
        x = (const float*)d_in[0];
        W = (const float*)d_in[1];
    } else {
        x = (const float*)d_in[1];
        W = (const float*)d_in[0];
    }
    float* out = (float*)d_out;

    init_kernel<<<76, 256>>>();

    for (int it = 0; it < 3; it++) {
        gemm_S_kernel<<<dim3(2, NSPLIT), 256>>>(x, W);
        reduce_squash_kernel<<<256, 512>>>(out, it == 2 ? 1 : 0);
        if (it < 2) {
            gemm_Ya_kernel<<<(KTOT + 63) / 64, 128>>>(x, W);
            compute_C_kernel<<<19, 128>>>();
        }
    }
}